// round 8
// baseline (speedup 1.0000x reference)
#include <cuda_runtime.h>
#include <math.h>

#define GN     8192
#define FIN    256
#define FOUT   64
#define NEG    0.01f
#define RBLK   256      // ranking blocks (scheduled FIRST)
#define SROWS  4        // rows per streaming block (register diet -> occupancy)
#define SBLK   (GN / SROWS)
#define NCHUNK 512      // sorted-order chunks
#define CSZ    16       // elements per chunk

// ---------------- device scratch ----------------
__device__ __align__(16) float g_Wh[GN * FOUT];
__device__ __align__(16) float    g_t[GN];    // s_tar
__device__ __align__(16) float    g_th[GN];   // -(s_src + a_b)
__device__ __align__(16) unsigned g_su[GN];   // sortable(t)
__device__ __align__(16) unsigned g_sth[GN];  // sortable(th)
__device__ __align__(16) float    g_P[GN];    // exp(s_src + a_b)
__device__ __align__(16) float    g_p[GN];    // exp(0.01*(s_src+a_b))
__device__ __align__(16) float    g_E[GN];    // exp(t)
__device__ __align__(16) float    g_e[GN];    // exp(0.01*t)
__device__ __align__(16) int      g_pos[GN];  // sorted pos -> original idx
__device__ __align__(16) int      g_k[GN];    // lower_bound(t_sorted, th_i)
__device__ __align__(16) float    g_cLoT[FOUT * NCHUNK];  // transposed [f][c]
__device__ __align__(16) float    g_cHiT[FOUT * NCHUNK];  // transposed [f][c]
__device__ __align__(16) float    g_Pre[NCHUNK * FOUT];        // exclusive prefix of cLo, [c][f]
__device__ __align__(16) float    g_Suf[(NCHUNK + 1) * FOUT];  // inclusive suffix of cHi, [c][f]
__device__ __align__(16) float    g_denom[GN];

__device__ __forceinline__ unsigned sortable(float f) {
    unsigned u = __float_as_uint(f);
    return (u & 0x80000000u) ? ~u : (u | 0x80000000u);
}

// ---------------- K1: Wh = H @ W + bW  + per-row scalar epilogue ----------------
__global__ __launch_bounds__(256) void k1_gemm_scal(const float* __restrict__ H,
                                                    const float* __restrict__ W,
                                                    const float* __restrict__ bW,
                                                    const float* __restrict__ aw,
                                                    const float* __restrict__ ab) {
    __shared__ float Hs[32][64];
    __shared__ float Ws[32][64];
    int tid = threadIdx.x;
    int row0 = blockIdx.x * 64;
    int tx = tid & 15, ty = tid >> 4;
    float acc[4][4] = {};
    for (int k0 = 0; k0 < FIN; k0 += 32) {
#pragma unroll
        for (int i = 0; i < 2; i++) {
            int idx = tid + i * 256;
            int r = idx >> 3, kq = idx & 7;
            float4 v = *(const float4*)(H + (size_t)(row0 + r) * FIN + k0 + kq * 4);
            Hs[kq * 4 + 0][r] = v.x;
            Hs[kq * 4 + 1][r] = v.y;
            Hs[kq * 4 + 2][r] = v.z;
            Hs[kq * 4 + 3][r] = v.w;
        }
#pragma unroll
        for (int i = 0; i < 2; i++) {
            int idx = tid + i * 256;
            int kk = idx >> 4, cq = idx & 15;
            *(float4*)&Ws[kk][cq * 4] =
                *(const float4*)(W + (size_t)(k0 + kk) * FOUT + cq * 4);
        }
        __syncthreads();
#pragma unroll
        for (int kk = 0; kk < 32; kk++) {
            float4 a = *(float4*)&Hs[kk][ty * 4];
            float4 b = *(float4*)&Ws[kk][tx * 4];
            acc[0][0] += a.x * b.x; acc[0][1] += a.x * b.y; acc[0][2] += a.x * b.z; acc[0][3] += a.x * b.w;
            acc[1][0] += a.y * b.x; acc[1][1] += a.y * b.y; acc[1][2] += a.y * b.z; acc[1][3] += a.y * b.w;
            acc[2][0] += a.z * b.x; acc[2][1] += a.z * b.y; acc[2][2] += a.z * b.z; acc[2][3] += a.z * b.w;
            acc[3][0] += a.w * b.x; acc[3][1] += a.w * b.y; acc[3][2] += a.w * b.z; acc[3][3] += a.w * b.w;
        }
        __syncthreads();
    }
    float4 bv = *(const float4*)(bW + tx * 4);
    float4 a1 = *(const float4*)(aw + tx * 4);
    float4 a2 = *(const float4*)(aw + FOUT + tx * 4);
    float ps[4], pt2[4];
#pragma unroll
    for (int u = 0; u < 4; u++) {
        float4 o;
        o.x = acc[u][0] + bv.x;
        o.y = acc[u][1] + bv.y;
        o.z = acc[u][2] + bv.z;
        o.w = acc[u][3] + bv.w;
        *(float4*)&g_Wh[(size_t)(row0 + ty * 4 + u) * FOUT + tx * 4] = o;
        ps[u]  = o.x * a1.x + o.y * a1.y + o.z * a1.z + o.w * a1.w;
        pt2[u] = o.x * a2.x + o.y * a2.y + o.z * a2.z + o.w * a2.w;
    }
#pragma unroll
    for (int o = 8; o; o >>= 1) {
#pragma unroll
        for (int u = 0; u < 4; u++) {
            ps[u]  += __shfl_xor_sync(0xffffffffu, ps[u], o);
            pt2[u] += __shfl_xor_sync(0xffffffffu, pt2[u], o);
        }
    }
    if (tx == 0) {
        float abv = ab[0];
#pragma unroll
        for (int u = 0; u < 4; u++) {
            int row = row0 + ty * 4 + u;
            float sb = ps[u] + abv;
            float star = pt2[u];
            float thv = -sb;
            g_t[row]   = star;
            g_th[row]  = thv;
            g_su[row]  = sortable(star);
            g_sth[row] = sortable(thv);
            g_P[row]   = expf(sb);
            g_p[row]   = expf(NEG * sb);
            g_E[row]   = expf(star);
            g_e[row]   = expf(NEG * star);
        }
    }
}

// ---------------- dummy (profiling-position shim) ----------------
__global__ void kdummy() {}

// ---- K2 (fused): blocks [0,RBLK) rank; blocks [RBLK, RBLK+SBLK) stream A ----
__global__ __launch_bounds__(256) void k2_rank_denom(const int* __restrict__ A) {
    __shared__ __align__(16) unsigned su[GN];   // 32 KB (ranking)
    __shared__ float s1[SROWS][8], s2[SROWS][8];
    int bid = blockIdx.x;
    int tid = threadIdx.x;
    int lane = tid & 31, w = tid >> 5;

    if (bid < RBLK) {
        // ---------------- ranking: 4 queries per warp, sortable-uint compares ----------------
        for (int i = tid; i < GN / 4; i += 256)
            ((uint4*)su)[i] = ((const uint4*)g_su)[i];
        __syncthreads();
        unsigned sq[4], sthv[4];
        int row[4];
#pragma unroll
        for (int q = 0; q < 4; q++) {
            row[q]  = bid * 32 + w * 4 + q;
            sq[q]   = g_su[row[q]];
            sthv[q] = g_sth[row[q]];
        }
        int cR[4] = {}, cK[4] = {};
#pragma unroll 2
        for (int i = 0; i < 64; i++) {
            uint4 v = ((uint4*)su)[i * 32 + lane];
            int m = (i * 32 + lane) * 4;
#pragma unroll
            for (int q = 0; q < 4; q++) {
                cR[q] += (v.x < sq[q]) + (v.x == sq[q] && (m + 0) < row[q]);
                cR[q] += (v.y < sq[q]) + (v.y == sq[q] && (m + 1) < row[q]);
                cR[q] += (v.z < sq[q]) + (v.z == sq[q] && (m + 2) < row[q]);
                cR[q] += (v.w < sq[q]) + (v.w == sq[q] && (m + 3) < row[q]);
                cK[q] += (v.x < sthv[q]) + (v.y < sthv[q]) + (v.z < sthv[q]) + (v.w < sthv[q]);
            }
        }
#pragma unroll
        for (int q = 0; q < 4; q++) {
#pragma unroll
            for (int o = 16; o; o >>= 1) {
                cR[q] += __shfl_xor_sync(0xffffffffu, cR[q], o);
                cK[q] += __shfl_xor_sync(0xffffffffu, cK[q], o);
            }
        }
        if (lane == 0) {
#pragma unroll
            for (int q = 0; q < 4; q++) {
                g_pos[cR[q]] = row[q];
                g_k[row[q]]  = cK[q];
            }
        }
    } else {
        // ---------------- denominator: predicated stream of A (268 MB) ----------------
        int ib = (bid - RBLK) * SROWS;
        float th[SROWS];
        float acc1[SROWS] = {}, acc2[SROWS] = {};
#pragma unroll
        for (int r = 0; r < SROWS; r++) th[r] = g_th[ib + r];
        // one base pointer; row stride (GN/4 int4 = 32 KB) folds into LDG immediates
        const int4* pA = (const int4*)A + (size_t)ib * (GN / 4) + tid;
        const float4* pE = (const float4*)g_E + tid;
        const float4* pe = (const float4*)g_e + tid;
        const float4* pt = (const float4*)g_t + tid;
#pragma unroll 1
        for (int it = 0; it < 8; it++) {
            float4 Ev = pE[it * 256];
            float4 ev = pe[it * 256];
            float4 tv = pt[it * 256];
            int4 a[SROWS];
#pragma unroll
            for (int r = 0; r < SROWS; r++)
                a[r] = __ldcs(pA + r * (GN / 4));
            pA += 256;
#pragma unroll
            for (int r = 0; r < SROWS; r++) {
                float thr = th[r];
                bool cx = tv.x >= thr, cy = tv.y >= thr, cz = tv.z >= thr, cw = tv.w >= thr;
                if (a[r].x &&  cx) acc1[r] += Ev.x;
                if (a[r].x && !cx) acc2[r] += ev.x;
                if (a[r].y &&  cy) acc1[r] += Ev.y;
                if (a[r].y && !cy) acc2[r] += ev.y;
                if (a[r].z &&  cz) acc1[r] += Ev.z;
                if (a[r].z && !cz) acc2[r] += ev.z;
                if (a[r].w &&  cw) acc1[r] += Ev.w;
                if (a[r].w && !cw) acc2[r] += ev.w;
            }
        }
#pragma unroll
        for (int r = 0; r < SROWS; r++) {
            float v1 = acc1[r], v2 = acc2[r];
#pragma unroll
            for (int o = 16; o; o >>= 1) {
                v1 += __shfl_xor_sync(0xffffffffu, v1, o);
                v2 += __shfl_xor_sync(0xffffffffu, v2, o);
            }
            if (lane == 0) { s1[r][w] = v1; s2[r][w] = v2; }
        }
        __syncthreads();
        if (tid < SROWS) {
            float d1 = 0.f, d2 = 0.f;
#pragma unroll
            for (int q = 0; q < 8; q++) { d1 += s1[tid][q]; d2 += s2[tid][q]; }
            int i = ib + tid;
            g_denom[i] = g_P[i] * d1 + g_p[i] * d2;
        }
    }
}

// ---------------- K3: per-chunk weighted sums (512 chunks x 16), transposed out ----------------
__global__ __launch_bounds__(256) void k3_chunks() {
    int c = blockIdx.x, tid = threadIdx.x;
    __shared__ int   sj[CSZ];
    __shared__ float swl[CSZ], swh[CSZ];
    __shared__ float sLo[4][FOUT], sHi[4][FOUT];
    if (tid < CSZ) {
        int jj = g_pos[c * CSZ + tid];
        sj[tid] = jj; swl[tid] = g_e[jj]; swh[tid] = g_E[jj];
    }
    __syncthreads();
    int rq = tid >> 6, f = tid & 63;
    float lo = 0.f, hi = 0.f;
#pragma unroll
    for (int u = 0; u < 4; u++) {
        int r = rq * 4 + u;
        float x = g_Wh[(size_t)sj[r] * FOUT + f];
        lo += swl[r] * x;
        hi += swh[r] * x;
    }
    sLo[rq][f] = lo; sHi[rq][f] = hi;
    __syncthreads();
    if (tid < FOUT) {
        float l = sLo[0][tid] + sLo[1][tid] + sLo[2][tid] + sLo[3][tid];
        float h = sHi[0][tid] + sHi[1][tid] + sHi[2][tid] + sHi[3][tid];
        g_cLoT[(size_t)tid * NCHUNK + c] = l;
        g_cHiT[(size_t)tid * NCHUNK + c] = h;
    }
}

// ---------------- K4: warp-per-feature register scan over 512 chunks ----------------
__global__ __launch_bounds__(256) void k4_scan() {
    int wf = threadIdx.x >> 5;
    int lane = threadIdx.x & 31;
    int f = blockIdx.x * 8 + wf;
    // ---- Pre: exclusive prefix of cLo over chunks ----
    {
        const float* src = g_cLoT + (size_t)f * NCHUNK + lane * 16;
        float v[16];
#pragma unroll
        for (int u = 0; u < 16; u += 4) {
            float4 q = *(const float4*)(src + u);
            v[u] = q.x; v[u + 1] = q.y; v[u + 2] = q.z; v[u + 3] = q.w;
        }
        float run = 0.f, inc[16];
#pragma unroll
        for (int u = 0; u < 16; u++) { run += v[u]; inc[u] = run; }
        float tot = run, scan = run;
#pragma unroll
        for (int o = 1; o < 32; o <<= 1) {
            float n = __shfl_up_sync(0xffffffffu, scan, o);
            if (lane >= o) scan += n;
        }
        float off = scan - tot;
#pragma unroll
        for (int u = 0; u < 16; u++)
            g_Pre[(size_t)(lane * 16 + u) * FOUT + f] = off + (inc[u] - v[u]);
    }
    // ---- Suf: inclusive suffix of cHi = total - exclusive prefix ----
    {
        const float* src = g_cHiT + (size_t)f * NCHUNK + lane * 16;
        float v[16];
#pragma unroll
        for (int u = 0; u < 16; u += 4) {
            float4 q = *(const float4*)(src + u);
            v[u] = q.x; v[u + 1] = q.y; v[u + 2] = q.z; v[u + 3] = q.w;
        }
        float run = 0.f, inc[16];
#pragma unroll
        for (int u = 0; u < 16; u++) { run += v[u]; inc[u] = run; }
        float tot = run, scan = run;
#pragma unroll
        for (int o = 1; o < 32; o <<= 1) {
            float n = __shfl_up_sync(0xffffffffu, scan, o);
            if (lane >= o) scan += n;
        }
        float off = scan - tot;
        float total = __shfl_sync(0xffffffffu, scan, 31);
#pragma unroll
        for (int u = 0; u < 16; u++)
            g_Suf[(size_t)(lane * 16 + u) * FOUT + f] = total - (off + (inc[u] - v[u]));
        if (lane == 31) g_Suf[(size_t)NCHUNK * FOUT + f] = 0.f;
    }
}

// ---------------- K5: direct output (4 queries per block) ----------------
__global__ __launch_bounds__(256) void k5_out(float* __restrict__ out) {
    int tid = threadIdx.x;
    __shared__ int   sj[4][CSZ];
    __shared__ float sl[4][CSZ], sh[4][CSZ];
    if (tid < 64) {
        int q = tid >> 4, r = tid & 15;
        int iq = blockIdx.x * 4 + q;
        int kq = g_k[iq];
        int cq = min(kq >> 4, NCHUNK - 1);
        int jj = g_pos[cq * CSZ + r];
        sj[q][r] = jj; sl[q][r] = g_e[jj]; sh[q][r] = g_E[jj];
    }
    __syncthreads();
    int q = tid >> 6, f = tid & 63;
    int i = blockIdx.x * 4 + q;
    int k = g_k[i];
    int c = min(k >> 4, NCHUNK - 1);
    int o = k - (c << 4);
    float x[CSZ];
#pragma unroll
    for (int r = 0; r < CSZ; r++)
        x[r] = g_Wh[(size_t)sj[q][r] * FOUT + f];
    float lo = 0.f, hi = 0.f;
#pragma unroll
    for (int r = 0; r < CSZ; r++) {
        if (r < o) lo += sl[q][r] * x[r];
        else       hi += sh[q][r] * x[r];
    }
    float lo_t = g_Pre[c * FOUT + f] + lo;
    float hi_t = g_Suf[(c + 1) * FOUT + f] + hi;
    float num = g_P[i] * hi_t + g_p[i] * lo_t;
    float z = num / g_denom[i];
    out[(size_t)i * FOUT + f] = 1.0f / (1.0f + __expf(-z));
}

// ---------------- launch ----------------
extern "C" void kernel_launch(void* const* d_in, const int* in_sizes, int n_in,
                              void* d_out, int out_size) {
    const float* H  = (const float*)d_in[0];
    const int*   A  = (const int*)d_in[1];
    const float* W  = (const float*)d_in[2];
    const float* bW = (const float*)d_in[3];
    const float* aw = (const float*)d_in[4];
    const float* ab = (const float*)d_in[5];
    float* out = (float*)d_out;

    k1_gemm_scal<<<GN / 64, 256>>>(H, W, bW, aw, ab);
    kdummy<<<1, 32>>>();                     // shim: keeps k2 at profiled position
    kdummy<<<1, 32>>>();
    k2_rank_denom<<<RBLK + SBLK, 256>>>(A);
    k3_chunks<<<NCHUNK, 256>>>();
    k4_scan<<<FOUT / 8, 256>>>();
    k5_out<<<GN / 4, 256>>>(out);
}

// round 9
// speedup vs baseline: 1.0715x; 1.0715x over previous
#include <cuda_runtime.h>
#include <math.h>

#define GN     8192
#define FIN    256
#define FOUT   64
#define NEG    0.01f
#define RBLK   256      // ranking blocks (scheduled FIRST)
#define SROWS  4        // rows per streaming block
#define SBLK   (GN / SROWS)
#define NCHUNK 512      // sorted-order chunks
#define CSZ    16       // elements per chunk

// ---------------- device scratch ----------------
__device__ __align__(16) float g_Wh[GN * FOUT];
__device__ __align__(16) float    g_t[GN];    // s_tar
__device__ __align__(16) float    g_th[GN];   // -(s_src + a_b)
__device__ __align__(16) unsigned g_su[GN];   // sortable(t)
__device__ __align__(16) unsigned g_sth[GN];  // sortable(th)
__device__ __align__(16) float    g_P[GN];    // exp(s_src + a_b)
__device__ __align__(16) float    g_p[GN];    // exp(0.01*(s_src+a_b))
__device__ __align__(16) float    g_E[GN];    // exp(t)
__device__ __align__(16) float    g_e[GN];    // exp(0.01*t)
__device__ __align__(16) int      g_pos[GN];  // sorted pos -> original idx
__device__ __align__(16) int      g_k[GN];    // lower_bound(t_sorted, th_i)
__device__ __align__(16) float    g_cLoT[FOUT * NCHUNK];  // transposed [f][c]
__device__ __align__(16) float    g_cHiT[FOUT * NCHUNK];  // transposed [f][c]
__device__ __align__(16) float    g_Pre[NCHUNK * FOUT];        // exclusive prefix of cLo, [c][f]
__device__ __align__(16) float    g_Suf[(NCHUNK + 1) * FOUT];  // inclusive suffix of cHi, [c][f]
__device__ __align__(16) float    g_denom[GN];

__device__ __forceinline__ unsigned sortable(float f) {
    unsigned u = __float_as_uint(f);
    return (u & 0x80000000u) ? ~u : (u | 0x80000000u);
}

__device__ __forceinline__ unsigned smem_u32(const void* p) {
    unsigned a;
    asm("{ .reg .u64 t; cvta.to.shared.u64 t, %1; cvt.u32.u64 %0, t; }" : "=r"(a) : "l"(p));
    return a;
}
__device__ __forceinline__ void cpasync16(unsigned s, const void* g) {
    asm volatile("cp.async.cg.shared.global [%0], [%1], 16;" :: "r"(s), "l"(g));
}
__device__ __forceinline__ void cp_commit() {
    asm volatile("cp.async.commit_group;");
}
template <int N> __device__ __forceinline__ void cp_wait() {
    asm volatile("cp.async.wait_group %0;" :: "n"(N));
}

// ---------------- K1: Wh = H @ W + bW  + per-row scalar epilogue ----------------
__global__ __launch_bounds__(256) void k1_gemm_scal(const float* __restrict__ H,
                                                    const float* __restrict__ W,
                                                    const float* __restrict__ bW,
                                                    const float* __restrict__ aw,
                                                    const float* __restrict__ ab) {
    __shared__ float Hs[32][64];
    __shared__ float Ws[32][64];
    int tid = threadIdx.x;
    int row0 = blockIdx.x * 64;
    int tx = tid & 15, ty = tid >> 4;
    float acc[4][4] = {};
    for (int k0 = 0; k0 < FIN; k0 += 32) {
#pragma unroll
        for (int i = 0; i < 2; i++) {
            int idx = tid + i * 256;
            int r = idx >> 3, kq = idx & 7;
            float4 v = *(const float4*)(H + (size_t)(row0 + r) * FIN + k0 + kq * 4);
            Hs[kq * 4 + 0][r] = v.x;
            Hs[kq * 4 + 1][r] = v.y;
            Hs[kq * 4 + 2][r] = v.z;
            Hs[kq * 4 + 3][r] = v.w;
        }
#pragma unroll
        for (int i = 0; i < 2; i++) {
            int idx = tid + i * 256;
            int kk = idx >> 4, cq = idx & 15;
            *(float4*)&Ws[kk][cq * 4] =
                *(const float4*)(W + (size_t)(k0 + kk) * FOUT + cq * 4);
        }
        __syncthreads();
#pragma unroll
        for (int kk = 0; kk < 32; kk++) {
            float4 a = *(float4*)&Hs[kk][ty * 4];
            float4 b = *(float4*)&Ws[kk][tx * 4];
            acc[0][0] += a.x * b.x; acc[0][1] += a.x * b.y; acc[0][2] += a.x * b.z; acc[0][3] += a.x * b.w;
            acc[1][0] += a.y * b.x; acc[1][1] += a.y * b.y; acc[1][2] += a.y * b.z; acc[1][3] += a.y * b.w;
            acc[2][0] += a.z * b.x; acc[2][1] += a.z * b.y; acc[2][2] += a.z * b.z; acc[2][3] += a.z * b.w;
            acc[3][0] += a.w * b.x; acc[3][1] += a.w * b.y; acc[3][2] += a.w * b.z; acc[3][3] += a.w * b.w;
        }
        __syncthreads();
    }
    float4 bv = *(const float4*)(bW + tx * 4);
    float4 a1 = *(const float4*)(aw + tx * 4);
    float4 a2 = *(const float4*)(aw + FOUT + tx * 4);
    float ps[4], pt2[4];
#pragma unroll
    for (int u = 0; u < 4; u++) {
        float4 o;
        o.x = acc[u][0] + bv.x;
        o.y = acc[u][1] + bv.y;
        o.z = acc[u][2] + bv.z;
        o.w = acc[u][3] + bv.w;
        *(float4*)&g_Wh[(size_t)(row0 + ty * 4 + u) * FOUT + tx * 4] = o;
        ps[u]  = o.x * a1.x + o.y * a1.y + o.z * a1.z + o.w * a1.w;
        pt2[u] = o.x * a2.x + o.y * a2.y + o.z * a2.z + o.w * a2.w;
    }
#pragma unroll
    for (int o = 8; o; o >>= 1) {
#pragma unroll
        for (int u = 0; u < 4; u++) {
            ps[u]  += __shfl_xor_sync(0xffffffffu, ps[u], o);
            pt2[u] += __shfl_xor_sync(0xffffffffu, pt2[u], o);
        }
    }
    if (tx == 0) {
        float abv = ab[0];
#pragma unroll
        for (int u = 0; u < 4; u++) {
            int row = row0 + ty * 4 + u;
            float sb = ps[u] + abv;
            float star = pt2[u];
            float thv = -sb;
            g_t[row]   = star;
            g_th[row]  = thv;
            g_su[row]  = sortable(star);
            g_sth[row] = sortable(thv);
            g_P[row]   = expf(sb);
            g_p[row]   = expf(NEG * sb);
            g_E[row]   = expf(star);
            g_e[row]   = expf(NEG * star);
        }
    }
}

// ---------------- dummy (profiling-position shim) ----------------
__global__ void kdummy() {}

// ---- K2 (fused): blocks [0,RBLK) rank; blocks [RBLK, RBLK+SBLK) stream A
//      streaming side: cp.async double-buffered A staging in smem ----
__global__ __launch_bounds__(256) void k2_rank_denom(const int* __restrict__ A) {
    __shared__ __align__(16) int4 sA[2][256 * SROWS];  // 32 KB: 2 stages x (256 thr x 4 rows)
    __shared__ float s1[SROWS][8], s2[SROWS][8];
    int bid = blockIdx.x;
    int tid = threadIdx.x;
    int lane = tid & 31, w = tid >> 5;

    if (bid < RBLK) {
        // ---- ranking: 4 queries/warp, sortable-uint compares, straight from L1/L2 ----
        unsigned sq[4], sthv[4];
        int row[4];
#pragma unroll
        for (int q = 0; q < 4; q++) {
            row[q]  = bid * 32 + w * 4 + q;
            sq[q]   = g_su[row[q]];
            sthv[q] = g_sth[row[q]];
        }
        int cR[4] = {}, cK[4] = {};
        const uint4* pu = (const uint4*)g_su + lane;
#pragma unroll 4
        for (int i = 0; i < 64; i++) {
            uint4 v = __ldg(pu + i * 32);
            int m = (i * 32 + lane) * 4;
#pragma unroll
            for (int q = 0; q < 4; q++) {
                cR[q] += (v.x < sq[q]) + (v.x == sq[q] && (m + 0) < row[q]);
                cR[q] += (v.y < sq[q]) + (v.y == sq[q] && (m + 1) < row[q]);
                cR[q] += (v.z < sq[q]) + (v.z == sq[q] && (m + 2) < row[q]);
                cR[q] += (v.w < sq[q]) + (v.w == sq[q] && (m + 3) < row[q]);
                cK[q] += (v.x < sthv[q]) + (v.y < sthv[q]) + (v.z < sthv[q]) + (v.w < sthv[q]);
            }
        }
#pragma unroll
        for (int q = 0; q < 4; q++) {
#pragma unroll
            for (int o = 16; o; o >>= 1) {
                cR[q] += __shfl_xor_sync(0xffffffffu, cR[q], o);
                cK[q] += __shfl_xor_sync(0xffffffffu, cK[q], o);
            }
        }
        if (lane == 0) {
#pragma unroll
            for (int q = 0; q < 4; q++) {
                g_pos[cR[q]] = row[q];
                g_k[row[q]]  = cK[q];
            }
        }
    } else {
        // ---- denominator: cp.async pipelined stream of A (268 MB) ----
        int ib = (bid - RBLK) * SROWS;
        float th[SROWS];
        float acc1[SROWS] = {}, acc2[SROWS] = {};
#pragma unroll
        for (int r = 0; r < SROWS; r++) th[r] = g_th[ib + r];

        const int4* pA = (const int4*)A + (size_t)ib * (GN / 4) + tid;
        const float4* pE = (const float4*)g_E + tid;
        const float4* pe = (const float4*)g_e + tid;
        const float4* pt = (const float4*)g_t + tid;
        unsigned sbase = smem_u32(sA) + (unsigned)tid * 16;   // this thread's slot, stage 0, row 0
        // stage stride = 16 KB, row stride = 4 KB

        // prefetch iteration 0 into stage 0
#pragma unroll
        for (int r = 0; r < SROWS; r++)
            cpasync16(sbase + r * 4096u, pA + r * (GN / 4));
        cp_commit();

#pragma unroll 1
        for (int it = 0; it < 8; it++) {
            // issue next iteration into the other stage
            if (it < 7) {
                unsigned sn = sbase + ((it + 1) & 1) * 16384u;
                const int4* pn = pA + 256;
#pragma unroll
                for (int r = 0; r < SROWS; r++)
                    cpasync16(sn + r * 4096u, pn + r * (GN / 4));
                cp_commit();
            }
            // metadata loads overlap the wait
            float4 Ev = *pE; pE += 256;
            float4 ev = *pe; pe += 256;
            float4 tv = *pt; pt += 256;
            if (it < 7) cp_wait<1>(); else cp_wait<0>();

            const int4* sc = &sA[it & 1][tid];
#pragma unroll
            for (int r = 0; r < SROWS; r++) {
                int4 a = sc[r * 256];
                float thr = th[r];
                float mx = __int_as_float(a.x * 0x3f800000);
                float my = __int_as_float(a.y * 0x3f800000);
                float mz = __int_as_float(a.z * 0x3f800000);
                float mw = __int_as_float(a.w * 0x3f800000);
                bool cx = tv.x >= thr, cy = tv.y >= thr, cz = tv.z >= thr, cw = tv.w >= thr;
                acc1[r] = fmaf(mx, cx ? Ev.x : 0.f, acc1[r]);
                acc2[r] = fmaf(mx, cx ? 0.f : ev.x, acc2[r]);
                acc1[r] = fmaf(my, cy ? Ev.y : 0.f, acc1[r]);
                acc2[r] = fmaf(my, cy ? 0.f : ev.y, acc2[r]);
                acc1[r] = fmaf(mz, cz ? Ev.z : 0.f, acc1[r]);
                acc2[r] = fmaf(mz, cz ? 0.f : ev.z, acc2[r]);
                acc1[r] = fmaf(mw, cw ? Ev.w : 0.f, acc1[r]);
                acc2[r] = fmaf(mw, cw ? 0.f : ev.w, acc2[r]);
            }
            pA += 256;
        }
#pragma unroll
        for (int r = 0; r < SROWS; r++) {
            float v1 = acc1[r], v2 = acc2[r];
#pragma unroll
            for (int o = 16; o; o >>= 1) {
                v1 += __shfl_xor_sync(0xffffffffu, v1, o);
                v2 += __shfl_xor_sync(0xffffffffu, v2, o);
            }
            if (lane == 0) { s1[r][w] = v1; s2[r][w] = v2; }
        }
        __syncthreads();
        if (tid < SROWS) {
            float d1 = 0.f, d2 = 0.f;
#pragma unroll
            for (int q = 0; q < 8; q++) { d1 += s1[tid][q]; d2 += s2[tid][q]; }
            int i = ib + tid;
            g_denom[i] = g_P[i] * d1 + g_p[i] * d2;
        }
    }
}

// ---------------- K3: per-chunk weighted sums (512 chunks x 16), transposed out ----------------
__global__ __launch_bounds__(256) void k3_chunks() {
    int c = blockIdx.x, tid = threadIdx.x;
    __shared__ int   sj[CSZ];
    __shared__ float swl[CSZ], swh[CSZ];
    __shared__ float sLo[4][FOUT], sHi[4][FOUT];
    if (tid < CSZ) {
        int jj = g_pos[c * CSZ + tid];
        sj[tid] = jj; swl[tid] = g_e[jj]; swh[tid] = g_E[jj];
    }
    __syncthreads();
    int rq = tid >> 6, f = tid & 63;
    float lo = 0.f, hi = 0.f;
#pragma unroll
    for (int u = 0; u < 4; u++) {
        int r = rq * 4 + u;
        float x = g_Wh[(size_t)sj[r] * FOUT + f];
        lo += swl[r] * x;
        hi += swh[r] * x;
    }
    sLo[rq][f] = lo; sHi[rq][f] = hi;
    __syncthreads();
    if (tid < FOUT) {
        float l = sLo[0][tid] + sLo[1][tid] + sLo[2][tid] + sLo[3][tid];
        float h = sHi[0][tid] + sHi[1][tid] + sHi[2][tid] + sHi[3][tid];
        g_cLoT[(size_t)tid * NCHUNK + c] = l;
        g_cHiT[(size_t)tid * NCHUNK + c] = h;
    }
}

// ---------------- K4: warp-per-feature register scan over 512 chunks ----------------
__global__ __launch_bounds__(256) void k4_scan() {
    int wf = threadIdx.x >> 5;
    int lane = threadIdx.x & 31;
    int f = blockIdx.x * 8 + wf;
    // ---- Pre: exclusive prefix of cLo over chunks ----
    {
        const float* src = g_cLoT + (size_t)f * NCHUNK + lane * 16;
        float v[16];
#pragma unroll
        for (int u = 0; u < 16; u += 4) {
            float4 q = *(const float4*)(src + u);
            v[u] = q.x; v[u + 1] = q.y; v[u + 2] = q.z; v[u + 3] = q.w;
        }
        float run = 0.f, inc[16];
#pragma unroll
        for (int u = 0; u < 16; u++) { run += v[u]; inc[u] = run; }
        float tot = run, scan = run;
#pragma unroll
        for (int o = 1; o < 32; o <<= 1) {
            float n = __shfl_up_sync(0xffffffffu, scan, o);
            if (lane >= o) scan += n;
        }
        float off = scan - tot;
#pragma unroll
        for (int u = 0; u < 16; u++)
            g_Pre[(size_t)(lane * 16 + u) * FOUT + f] = off + (inc[u] - v[u]);
    }
    // ---- Suf: inclusive suffix of cHi = total - exclusive prefix ----
    {
        const float* src = g_cHiT + (size_t)f * NCHUNK + lane * 16;
        float v[16];
#pragma unroll
        for (int u = 0; u < 16; u += 4) {
            float4 q = *(const float4*)(src + u);
            v[u] = q.x; v[u + 1] = q.y; v[u + 2] = q.z; v[u + 3] = q.w;
        }
        float run = 0.f, inc[16];
#pragma unroll
        for (int u = 0; u < 16; u++) { run += v[u]; inc[u] = run; }
        float tot = run, scan = run;
#pragma unroll
        for (int o = 1; o < 32; o <<= 1) {
            float n = __shfl_up_sync(0xffffffffu, scan, o);
            if (lane >= o) scan += n;
        }
        float off = scan - tot;
        float total = __shfl_sync(0xffffffffu, scan, 31);
#pragma unroll
        for (int u = 0; u < 16; u++)
            g_Suf[(size_t)(lane * 16 + u) * FOUT + f] = total - (off + (inc[u] - v[u]));
        if (lane == 31) g_Suf[(size_t)NCHUNK * FOUT + f] = 0.f;
    }
}

// ---------------- K5: direct output (4 queries per block) ----------------
__global__ __launch_bounds__(256) void k5_out(float* __restrict__ out) {
    int tid = threadIdx.x;
    __shared__ int   sj[4][CSZ];
    __shared__ float sl[4][CSZ], sh[4][CSZ];
    if (tid < 64) {
        int q = tid >> 4, r = tid & 15;
        int iq = blockIdx.x * 4 + q;
        int kq = g_k[iq];
        int cq = min(kq >> 4, NCHUNK - 1);
        int jj = g_pos[cq * CSZ + r];
        sj[q][r] = jj; sl[q][r] = g_e[jj]; sh[q][r] = g_E[jj];
    }
    __syncthreads();
    int q = tid >> 6, f = tid & 63;
    int i = blockIdx.x * 4 + q;
    int k = g_k[i];
    int c = min(k >> 4, NCHUNK - 1);
    int o = k - (c << 4);
    float x[CSZ];
#pragma unroll
    for (int r = 0; r < CSZ; r++)
        x[r] = g_Wh[(size_t)sj[q][r] * FOUT + f];
    float lo = 0.f, hi = 0.f;
#pragma unroll
    for (int r = 0; r < CSZ; r++) {
        if (r < o) lo += sl[q][r] * x[r];
        else       hi += sh[q][r] * x[r];
    }
    float lo_t = g_Pre[c * FOUT + f] + lo;
    float hi_t = g_Suf[(c + 1) * FOUT + f] + hi;
    float num = g_P[i] * hi_t + g_p[i] * lo_t;
    float z = num / g_denom[i];
    out[(size_t)i * FOUT + f] = 1.0f / (1.0f + __expf(-z));
}

// ---------------- launch ----------------
extern "C" void kernel_launch(void* const* d_in, const int* in_sizes, int n_in,
                              void* d_out, int out_size) {
    const float* H  = (const float*)d_in[0];
    const int*   A  = (const int*)d_in[1];
    const float* W  = (const float*)d_in[2];
    const float* bW = (const float*)d_in[3];
    const float* aw = (const float*)d_in[4];
    const float* ab = (const float*)d_in[5];
    float* out = (float*)d_out;

    k1_gemm_scal<<<GN / 64, 256>>>(H, W, bW, aw, ab);
    kdummy<<<1, 32>>>();                     // shim: keeps k2 at profiled position
    kdummy<<<1, 32>>>();
    k2_rank_denom<<<RBLK + SBLK, 256>>>(A);
    k3_chunks<<<NCHUNK, 256>>>();
    k4_scan<<<FOUT / 8, 256>>>();
    k5_out<<<GN / 4, 256>>>(out);
}